// round 3
// baseline (speedup 1.0000x reference)
#include <cuda_runtime.h>
#include <math.h>

#define N_CLUSTS 50000

// Scratch (static device arrays — allowed; cudaMalloc is not)
__device__ float4 g_acc[N_CLUSTS * 3];   // [sx,sy,sz,cnt] [sxx,sxy,sxz,syy] [syz,szz,-,-]
__device__ float  g_sc[N_CLUSTS];        // sum x0*np0
__device__ float4 g_cv[N_CLUSTS * 2];    // [cx,cy,cz,dirwt] [v0x,v0y,v0z,multi]

// Vectorized global reductions (PTX ISA 8.1+, sm_90a/sm_100a).
__device__ __forceinline__ void red_add_v4(float4* addr, float a, float b, float c, float d) {
    asm volatile("red.global.add.v4.f32 [%0], {%1,%2,%3,%4};"
                 :: "l"(addr), "f"(a), "f"(b), "f"(c), "f"(d) : "memory");
}
__device__ __forceinline__ void red_add_v2(float4* addr, float a, float b) {
    asm volatile("red.global.add.v2.f32 [%0], {%1,%2};"
                 :: "l"(addr), "f"(a), "f"(b) : "memory");
}

// ---------------------------------------------------------------------------
__global__ void k_zero() {
    int i = blockIdx.x * blockDim.x + threadIdx.x;
    if (i < N_CLUSTS * 3) g_acc[i] = make_float4(0.f, 0.f, 0.f, 0.f);
    if (i < N_CLUSTS * 2) g_cv[i]  = make_float4(0.f, 0.f, 0.f, 0.f);
    if (i < N_CLUSTS)     g_sc[i]  = 0.f;
}

// ---------------------------------------------------------------------------
// Pass 1: per-voxel accumulation of count, first and second raw moments.
// 3 vector red-ops per voxel instead of 10 scalar atomics.
__global__ void k_accum(const float* __restrict__ data,
                        const int* __restrict__ cid, int n) {
    int i = blockIdx.x * blockDim.x + threadIdx.x;
    if (i >= n) return;
    int c = cid[i];
    const float* p = data + (size_t)i * 6;
    float x = __ldg(p + 1);
    float y = __ldg(p + 2);
    float z = __ldg(p + 3);
    float4* base = &g_acc[c * 3];
    red_add_v4(base,     x,     y,     z,     1.0f);
    red_add_v4(base + 1, x * x, x * y, x * z, y * y);
    red_add_v2(base + 2, y * z, z * z);
}

// ---------------------------------------------------------------------------
// Per-cluster: center, covariance A, 3x3 Jacobi eigensolve, B, dirwt.
// Writes center/B/size into out; stashes (center,dirwt) and (v0,multi) for pass 2.
__global__ void k_eig(float* __restrict__ out) {
    int c = blockIdx.x * blockDim.x + threadIdx.x;
    if (c >= N_CLUSTS) return;

    float4 s0 = g_acc[c * 3 + 0];
    float4 s1 = g_acc[c * 3 + 1];
    float4 s2 = g_acc[c * 3 + 2];
    float cnt = s0.w;
    float inv = 1.f / fmaxf(cnt, 1.f);
    float cx = s0.x * inv, cy = s0.y * inv, cz = s0.z * inv;

    // A = Sum(x x^T) - cnt * c c^T   (exact centered covariance for cnt>=1)
    float a00 = s1.x - cnt * cx * cx;
    float a01 = s1.y - cnt * cx * cy;
    float a02 = s1.z - cnt * cx * cz;
    float a11 = s1.w - cnt * cy * cy;
    float a12 = s2.x - cnt * cy * cz;
    float a22 = s2.y - cnt * cz * cz;

    // --- cyclic Jacobi, 8 sweeps (quadratic convergence; plenty) ---
    float A[3][3] = {{a00, a01, a02}, {a01, a11, a12}, {a02, a12, a22}};
    float V[3][3] = {{1.f, 0.f, 0.f}, {0.f, 1.f, 0.f}, {0.f, 0.f, 1.f}};
    const int Pp[3] = {0, 0, 1};
    const int Qq[3] = {1, 2, 2};
    #pragma unroll 1
    for (int sweep = 0; sweep < 8; sweep++) {
        #pragma unroll
        for (int r = 0; r < 3; r++) {
            int p = Pp[r], q = Qq[r];
            float apq = A[p][q];
            if (fabsf(apq) > 0.f) {
                float tau = (A[q][q] - A[p][p]) / (2.f * apq);
                float t = copysignf(1.f / (fabsf(tau) + sqrtf(1.f + tau * tau)), tau);
                float cth = rsqrtf(1.f + t * t);
                float sth = t * cth;
                #pragma unroll
                for (int k = 0; k < 3; k++) {   // columns: A = A*G
                    float akp = A[k][p], akq = A[k][q];
                    A[k][p] = cth * akp - sth * akq;
                    A[k][q] = sth * akp + cth * akq;
                }
                #pragma unroll
                for (int k = 0; k < 3; k++) {   // rows: A = G^T*A
                    float apk = A[p][k], aqk = A[q][k];
                    A[p][k] = cth * apk - sth * aqk;
                    A[q][k] = sth * apk + cth * aqk;
                }
                #pragma unroll
                for (int k = 0; k < 3; k++) {   // V = V*G
                    float vkp = V[k][p], vkq = V[k][q];
                    V[k][p] = cth * vkp - sth * vkq;
                    V[k][q] = sth * vkp + cth * vkq;
                }
            }
        }
    }

    float w[3] = {A[0][0], A[1][1], A[2][2]};
    // argmax eigenvalue
    int i2 = (w[1] > w[0]) ? 1 : 0;
    if (w[2] > w[i2]) i2 = 2;
    int ia = (i2 + 1) % 3, ib = (i2 + 2) % 3;
    float wmid = fmaxf(w[ia], w[ib]);   // middle eigenvalue
    float w2v = w[i2];

    float safe = (w2v > 0.f) ? w2v : 1.f;
    float dirwt = 1.f - wmid / safe;
    bool multi = (cnt >= 2.f);
    float bm = multi ? (1.f / safe) : 0.f;

    float v0x = V[0][i2], v0y = V[1][i2], v0z = V[2][i2];

    float* o = out + (size_t)c * 16;
    o[0]  = cx; o[1] = cy; o[2] = cz;
    o[3]  = a00 * bm; o[4]  = a01 * bm; o[5]  = a02 * bm;
    o[6]  = a01 * bm; o[7]  = a11 * bm; o[8]  = a12 * bm;
    o[9]  = a02 * bm; o[10] = a12 * bm; o[11] = a22 * bm;
    o[15] = cnt;

    g_cv[2 * c + 0] = make_float4(cx, cy, cz, dirwt);
    g_cv[2 * c + 1] = make_float4(v0x, v0y, v0z, multi ? 1.f : 0.f);
}

// ---------------------------------------------------------------------------
// Pass 2: sc = segment_sum(x0 * ||x - c - x0*v0||)
__global__ void k_sc(const float* __restrict__ data,
                     const int* __restrict__ cid, int n) {
    int i = blockIdx.x * blockDim.x + threadIdx.x;
    if (i >= n) return;
    int c = cid[i];
    const float* p = data + (size_t)i * 6;
    float x = __ldg(p + 1);
    float y = __ldg(p + 2);
    float z = __ldg(p + 3);
    float4 ct = __ldg(&g_cv[2 * c + 0]);
    float4 vv = __ldg(&g_cv[2 * c + 1]);
    float dx = x - ct.x, dy = y - ct.y, dz = z - ct.z;
    float x0 = dx * vv.x + dy * vv.y + dz * vv.z;
    float px = dx - x0 * vv.x;
    float py = dy - x0 * vv.y;
    float pz = dz - x0 * vv.z;
    float np0 = sqrtf(px * px + py * py + pz * pz);
    atomicAdd(&g_sc[c], x0 * np0);
}

// ---------------------------------------------------------------------------
// Finalize v0: sign flip by sc, scale by dirwt, mask by multi.
__global__ void k_final(float* __restrict__ out) {
    int c = blockIdx.x * blockDim.x + threadIdx.x;
    if (c >= N_CLUSTS) return;
    float sc = g_sc[c];
    float4 ct = g_cv[2 * c + 0];
    float4 vv = g_cv[2 * c + 1];
    float s = (sc < 0.f) ? -1.f : 1.f;
    float f = s * ct.w * vv.w;   // sign * dirwt * multi
    float* o = out + (size_t)c * 16;
    o[12] = vv.x * f;
    o[13] = vv.y * f;
    o[14] = vv.z * f;
}

// ---------------------------------------------------------------------------
extern "C" void kernel_launch(void* const* d_in, const int* in_sizes, int n_in,
                              void* d_out, int out_size) {
    const float* data = (const float*)d_in[0];
    const int*   cid  = (const int*)d_in[1];
    float* out = (float*)d_out;
    int n = in_sizes[1];   // number of voxels (clust_ids element count)

    k_zero <<<(N_CLUSTS * 3 + 255) / 256, 256>>>();
    k_accum<<<(n + 255) / 256, 256>>>(data, cid, n);
    k_eig  <<<(N_CLUSTS + 127) / 128, 128>>>(out);
    k_sc   <<<(n + 255) / 256, 256>>>(data, cid, n);
    k_final<<<(N_CLUSTS + 255) / 256, 256>>>(out);
}